// round 13
// baseline (speedup 1.0000x reference)
#include <cuda_runtime.h>
#include <stdint.h>

// LSTM: H=50, input 1, T=1024, B independent batch elements.
// R=2 row-blocking x M=7 weight-shared batches, 2 blocks/SM, one full wave.
// NEW: the 7 batches are split into groups A (0..3) and B (4..6) whose
// recurrences are synchronized by SEPARATE named barriers (arrive after the
// h write, sync before the h read, parity-alternating ids). Each warp always
// has the other group's 700-cycle FMA burst to issue while a group's tail /
// barrier settles -> barrier skew and the MUFU tail leave the critical path.
//   thread 2j   (even lane): rows j    (i-gate), j+100 (g-gate)
//   thread 2j+1 (odd  lane): rows j+50 (f-gate), j+150 (o-gate)
// Even lane computes p = sig(i)*tanh(g); shfl_xor(1) hands it to the odd
// lane, which holds c privately and writes h (double-buffered).
// Gate order (PyTorch): i[0:50], f[50:100], g[100:150], o[150:200].

#define HH 50
#define TT 1024
#define BT 128
#define MM 7
#define MA 4          // group A = batches [0,4), group B = [4,7)
#define HSTRIDE 64    // padded h row (floats)

typedef unsigned long long ull;

__device__ __forceinline__ float tanha(float x) {
    float y;
    asm("tanh.approx.f32 %0, %1;" : "=f"(y) : "f"(x));
    return y;
}
__device__ __forceinline__ float sigt(float x) {
    return fmaf(0.5f, tanha(0.5f * x), 0.5f);   // sigmoid via tanh
}
__device__ __forceinline__ void fma2(ull& d, ull a, ull b) {
    asm("fma.rn.f32x2 %0, %1, %2, %0;" : "+l"(d) : "l"(a), "l"(b));
}
__device__ __forceinline__ ull pack2(float lo, float hi) {
    return ((ull)__float_as_uint(hi) << 32) | (ull)__float_as_uint(lo);
}
__device__ __forceinline__ float sum2(ull a) {
    return __uint_as_float((unsigned)a) + __uint_as_float((unsigned)(a >> 32));
}
// Named barriers: count 256 = 128 bar.arrive + 128 bar.sync arrivals/phase.
__device__ __forceinline__ void bar_syncn(int id) {
    asm volatile("bar.sync %0, 256;" :: "r"(id) : "memory");
}
__device__ __forceinline__ void bar_arriven(int id) {
    asm volatile("bar.arrive %0, 256;" :: "r"(id) : "memory");
}

// One group's full timestep: FMA burst + activations + c/h update.
template<int M0, int MC>
__device__ __forceinline__ void group_step(
    const float* __restrict__ xcol,          // &x_sh[0][t], row stride TT
    const ulonglong2* __restrict__ hb,       // read buf base (ulonglong2)
    float* __restrict__ hw,                  // &h_sh[wb][0][jj]
    const ull* __restrict__ wA, const ull* __restrict__ wB,
    float wihA, float wihB, float biasA, float biasB,
    float* __restrict__ c, int odd, int upd)
{
    ull aA[MC], aB[MC];
    #pragma unroll
    for (int m = 0; m < MC; m++) {
        const float xt = xcol[(M0 + m) * TT];
        aA[m] = (ull)__float_as_uint(fmaf(xt, wihA, biasA));   // hi half = +0
        aB[m] = (ull)__float_as_uint(fmaf(xt, wihB, biasB));
    }
    #pragma unroll
    for (int q = 0; q < 13; q++) {
        #pragma unroll
        for (int m = 0; m < MC; m++) {
            ulonglong2 hv = hb[(M0 + m) * (HSTRIDE / 4) + q];  // bcast LDS.128
            fma2(aA[m], wA[2 * q],     hv.x);                  // folded chains
            fma2(aA[m], wA[2 * q + 1], hv.y);
            fma2(aB[m], wB[2 * q],     hv.x);
            fma2(aB[m], wB[2 * q + 1], hv.y);
        }
    }
    #pragma unroll
    for (int m = 0; m < MC; m++) {
        const float sA = sum2(aA[m]);                 // i or f
        const float sB = sum2(aB[m]);                 // g or o
        const float act0 = sigt(sA);                  // sig(i) / sig(f)
        const float act1 = odd ? sigt(sB) : tanha(sB);// sig(o) / tanh(g)
        const float p = act0 * act1;                  // even: sig(i)*tanh(g)
        const float q2 = __shfl_xor_sync(0xFFFFFFFFu, p, 1);
        if (upd) {
            c[M0 + m] = fmaf(act0, c[M0 + m], q2);    // sig(f)*c + i*g
            hw[(M0 + m) * HSTRIDE] = act1 * tanha(c[M0 + m]);  // sig(o)*tanh(c)
        }
    }
}

__global__ void __launch_bounds__(BT, 2)
lstm_kernel(const float* __restrict__ x,      // [B, T, 1]
            const float* __restrict__ W_ih,   // [200, 1]
            const float* __restrict__ W_hh,   // [200, 50]
            const float* __restrict__ b_ih,   // [200]
            const float* __restrict__ b_hh,   // [200]
            const float* __restrict__ W_lin,  // [1, 50]
            const float* __restrict__ b_lin,  // [1]
            float* __restrict__ out,          // [B, 1]
            int B)
{
    __shared__ __align__(16) float h_sh[2][MM][HSTRIDE];  // [buf][batch][idx]
    __shared__ float x_sh[MM][TT];

    const int tid = threadIdx.x;
    const int b0  = blockIdx.x * MM;
    const int jj  = tid >> 1;            // hidden index 0..63
    const int odd = tid & 1;             // 0: (i,g)   1: (f,o)
    const bool active = (jj < HH);
    const int  upd = odd & (int)active;

    for (int i = tid; i < MM * TT; i += BT) {
        const int m = i / TT, t = i & (TT - 1);
        x_sh[m][t] = (b0 + m < B) ? x[(size_t)(b0 + m) * TT + t] : 0.0f;
    }
    for (int i = tid; i < 2 * MM * HSTRIDE; i += BT) ((float*)h_sh)[i] = 0.0f;

    // Rows: rA = i or f, rB = g or o (zero weights if inactive).
    const int rA = jj + odd * 50;
    const int rB = rA + 100;
    ull wA[26], wB[26];
    float wihA = 0.0f, wihB = 0.0f, biasA = 0.0f, biasB = 0.0f;
    if (active) {
        wihA  = W_ih[rA];            wihB  = W_ih[rB];
        biasA = b_ih[rA] + b_hh[rA]; biasB = b_ih[rB] + b_hh[rB];
    }
    #pragma unroll
    for (int q = 0; q < 26; q++) {
        float l0 = (active && 2 * q     < HH) ? W_hh[rA * HH + 2 * q]     : 0.0f;
        float l1 = (active && 2 * q + 1 < HH) ? W_hh[rA * HH + 2 * q + 1] : 0.0f;
        float m0 = (active && 2 * q     < HH) ? W_hh[rB * HH + 2 * q]     : 0.0f;
        float m1 = (active && 2 * q + 1 < HH) ? W_hh[rB * HH + 2 * q + 1] : 0.0f;
        wA[q] = pack2(l0, l1);
        wB[q] = pack2(m0, m1);
    }
    float c[MM];
    #pragma unroll
    for (int m = 0; m < MM; m++) c[m] = 0.0f;    // cell state, odd lanes
    __syncthreads();

    // Prime parity-0 barriers (ids: A -> 1,2   B -> 3,4).
    bar_arriven(1);
    bar_arriven(3);

    #pragma unroll 1
    for (int t = 0; t < TT; t++) {
        const int p  = t & 1;
        const ulonglong2* hb = (const ulonglong2*)h_sh[p];
        float* hw = &h_sh[p ^ 1][0][jj];
        const float* xcol = &x_sh[0][t];

        // Group A
        bar_syncn(1 + p);                 // h_A(t) writes visible
        group_step<0, MA>(xcol, hb, hw, wA, wB,
                          wihA, wihB, biasA, biasB, c, odd, upd);
        bar_arriven(1 + (p ^ 1));         // h_A(t+1) written

        // Group B (independent recurrence -> fills A's barrier shadow)
        bar_syncn(3 + p);
        group_step<MA, MM - MA>(xcol, hb, hw, wA, wB,
                                wihA, wihB, biasA, biasB, c, odd, upd);
        bar_arriven(3 + (p ^ 1));
    }
    __syncthreads();

    // Final h in buffer (1023&1)^1 == 0. Linear head, one thread per batch.
    if (tid < MM && b0 + tid < B) {
        float s = b_lin[0];
        #pragma unroll 1
        for (int k = 0; k < HH; k++) s = fmaf(h_sh[0][tid][k], W_lin[k], s);
        out[b0 + tid] = s;
    }
}

extern "C" void kernel_launch(void* const* d_in, const int* in_sizes, int n_in,
                              void* d_out, int out_size) {
    const float* x     = (const float*)d_in[0];
    const float* W_ih  = (const float*)d_in[1];
    const float* W_hh  = (const float*)d_in[2];
    const float* b_ih  = (const float*)d_in[3];
    const float* b_hh  = (const float*)d_in[4];
    const float* W_lin = (const float*)d_in[5];
    const float* b_lin = (const float*)d_in[6];
    float* out = (float*)d_out;

    int B = in_sizes[0] / TT;
    int grid = (B + MM - 1) / MM;
    lstm_kernel<<<grid, BT>>>(x, W_ih, W_hh, b_ih, b_hh, W_lin, b_lin, out, B);
}

// round 14
// speedup vs baseline: 1.0815x; 1.0815x over previous
#include <cuda_runtime.h>
#include <stdint.h>

// LSTM: H=50, input 1, T=1024, B independent batch elements.
// R=2 row-blocking x M=7 weight-shared batches, 2 blocks/SM, one full wave
// (grid = ceil(2048/7) = 293 <= 296). ONE __syncthreads per step.
// NEW vs R12: the 13-chunk h-broadcast loop is explicitly software-pipelined
// (prefetch chunk q+1's 7 LDS.128 before issuing chunk q's 28 FFMA2) so every
// shared-memory load has a ~56-cycle FMA burst covering its 29-cycle latency.
//   thread 2j   (even lane): rows j    (i-gate), j+100 (g-gate)
//   thread 2j+1 (odd  lane): rows j+50 (f-gate), j+150 (o-gate)
// Even lane computes p = sig(i)*tanh(g); shfl_xor(1) hands it to the odd
// lane, which holds c privately and writes h (double-buffered h_sh).
// MUFU tanh.approx activations (sigmoid = 0.5*tanh(x/2)+0.5).
// Gate order (PyTorch): i[0:50], f[50:100], g[100:150], o[150:200].

#define HH 50
#define TT 1024
#define BT 128
#define MM 7
#define HSTRIDE 64    // padded h row (floats)

typedef unsigned long long ull;

__device__ __forceinline__ float tanha(float x) {
    float y;
    asm("tanh.approx.f32 %0, %1;" : "=f"(y) : "f"(x));
    return y;
}
__device__ __forceinline__ float sigt(float x) {
    return fmaf(0.5f, tanha(0.5f * x), 0.5f);   // sigmoid via tanh
}
__device__ __forceinline__ void fma2(ull& d, ull a, ull b) {
    asm("fma.rn.f32x2 %0, %1, %2, %0;" : "+l"(d) : "l"(a), "l"(b));
}
__device__ __forceinline__ ull pack2(float lo, float hi) {
    return ((ull)__float_as_uint(hi) << 32) | (ull)__float_as_uint(lo);
}
__device__ __forceinline__ float sum2(ull a) {
    return __uint_as_float((unsigned)a) + __uint_as_float((unsigned)(a >> 32));
}

__global__ void __launch_bounds__(BT, 2)
lstm_kernel(const float* __restrict__ x,      // [B, T, 1]
            const float* __restrict__ W_ih,   // [200, 1]
            const float* __restrict__ W_hh,   // [200, 50]
            const float* __restrict__ b_ih,   // [200]
            const float* __restrict__ b_hh,   // [200]
            const float* __restrict__ W_lin,  // [1, 50]
            const float* __restrict__ b_lin,  // [1]
            float* __restrict__ out,          // [B, 1]
            int B)
{
    __shared__ __align__(16) float h_sh[2][MM][HSTRIDE];  // [buf][batch][idx]
    __shared__ float x_sh[MM][TT];

    const int tid = threadIdx.x;
    const int b0  = blockIdx.x * MM;
    const int jj  = tid >> 1;            // hidden index 0..63
    const int odd = tid & 1;             // 0: (i,g)   1: (f,o)
    const bool active = (jj < HH);
    const int  upd = odd & (int)active;

    for (int i = tid; i < MM * TT; i += BT) {
        const int m = i / TT, t = i & (TT - 1);
        x_sh[m][t] = (b0 + m < B) ? x[(size_t)(b0 + m) * TT + t] : 0.0f;
    }
    for (int i = tid; i < 2 * MM * HSTRIDE; i += BT) ((float*)h_sh)[i] = 0.0f;

    // Rows: rA = i or f, rB = g or o (zero weights if inactive).
    const int rA = jj + odd * 50;
    const int rB = rA + 100;
    ull wA[26], wB[26];
    float wihA = 0.0f, wihB = 0.0f, biasA = 0.0f, biasB = 0.0f;
    if (active) {
        wihA  = W_ih[rA];            wihB  = W_ih[rB];
        biasA = b_ih[rA] + b_hh[rA]; biasB = b_ih[rB] + b_hh[rB];
    }
    #pragma unroll
    for (int q = 0; q < 26; q++) {
        float l0 = (active && 2 * q     < HH) ? W_hh[rA * HH + 2 * q]     : 0.0f;
        float l1 = (active && 2 * q + 1 < HH) ? W_hh[rA * HH + 2 * q + 1] : 0.0f;
        float m0 = (active && 2 * q     < HH) ? W_hh[rB * HH + 2 * q]     : 0.0f;
        float m1 = (active && 2 * q + 1 < HH) ? W_hh[rB * HH + 2 * q + 1] : 0.0f;
        wA[q] = pack2(l0, l1);
        wB[q] = pack2(m0, m1);
    }
    float c[MM];
    #pragma unroll
    for (int m = 0; m < MM; m++) c[m] = 0.0f;    // cell state, odd lanes
    __syncthreads();

    #pragma unroll 1
    for (int t = 0; t < TT; t++) {
        const int rb = t & 1;
        ull aA[MM], aB[MM];
        #pragma unroll
        for (int m = 0; m < MM; m++) {
            const float xt = x_sh[m][t];
            aA[m] = (ull)__float_as_uint(fmaf(xt, wihA, biasA));  // hi = +0
            aB[m] = (ull)__float_as_uint(fmaf(xt, wihB, biasB));
        }
        const ulonglong2* hb = (const ulonglong2*)h_sh[rb];

        // ---- software-pipelined h-broadcast loop ----
        ulonglong2 hv[MM];                         // current chunk (in regs)
        #pragma unroll
        for (int m = 0; m < MM; m++)
            hv[m] = hb[m * (HSTRIDE / 4)];
        #pragma unroll
        for (int q = 0; q < 13; q++) {
            ulonglong2 hn[MM];
            if (q < 12) {                          // prefetch next chunk
                #pragma unroll
                for (int m = 0; m < MM; m++)
                    hn[m] = hb[m * (HSTRIDE / 4) + q + 1];
            }
            #pragma unroll
            for (int m = 0; m < MM; m++) {
                fma2(aA[m], wA[2 * q],     hv[m].x);   // folded chains
                fma2(aA[m], wA[2 * q + 1], hv[m].y);
                fma2(aB[m], wB[2 * q],     hv[m].x);
                fma2(aB[m], wB[2 * q + 1], hv[m].y);
            }
            if (q < 12) {
                #pragma unroll
                for (int m = 0; m < MM; m++) hv[m] = hn[m];
            }
        }

        float* hw = &h_sh[rb ^ 1][0][jj];
        #pragma unroll
        for (int m = 0; m < MM; m++) {
            const float sA = sum2(aA[m]);          // i or f
            const float sB = sum2(aB[m]);          // g or o
            const float act0 = sigt(sA);                       // sig(i)/sig(f)
            const float act1 = odd ? sigt(sB) : tanha(sB);     // sig(o)/tanh(g)
            const float p = act0 * act1;           // even lane: sig(i)*tanh(g)
            const float q2 = __shfl_xor_sync(0xFFFFFFFFu, p, 1);
            if (upd) {
                c[m] = fmaf(act0, c[m], q2);       // sig(f)*c + sig(i)*tanh(g)
                hw[m * HSTRIDE] = act1 * tanha(c[m]);   // sig(o)*tanh(c)
            }
        }
        __syncthreads();
    }

    // Final h in buffer (1023&1)^1 == 0. Linear head, one thread per batch.
    if (tid < MM && b0 + tid < B) {
        float s = b_lin[0];
        #pragma unroll 1
        for (int k = 0; k < HH; k++) s = fmaf(h_sh[0][tid][k], W_lin[k], s);
        out[b0 + tid] = s;
    }
}

extern "C" void kernel_launch(void* const* d_in, const int* in_sizes, int n_in,
                              void* d_out, int out_size) {
    const float* x     = (const float*)d_in[0];
    const float* W_ih  = (const float*)d_in[1];
    const float* W_hh  = (const float*)d_in[2];
    const float* b_ih  = (const float*)d_in[3];
    const float* b_hh  = (const float*)d_in[4];
    const float* W_lin = (const float*)d_in[5];
    const float* b_lin = (const float*)d_in[6];
    float* out = (float*)d_out;

    int B = in_sizes[0] / TT;
    int grid = (B + MM - 1) / MM;
    lstm_kernel<<<grid, BT>>>(x, W_ih, W_hh, b_ih, b_hh, W_lin, b_lin, out, B);
}